// round 1
// baseline (speedup 1.0000x reference)
#include <cuda_runtime.h>
#include <math.h>

// Problem: x (4096, 8192) f32 row-major, a scalar f32.
// z = -exp(a) * x ; out = sparsemax(z, axis=0)  (per-column simplex projection)
//
// Strategy:
//  * 1 block = 8 columns, 512 threads, full column tile (4096x8 f32) held in
//    registers (64 floats/thread via 16 float4 loads, 32B-sector aligned).
//  * per-column max via parity shuffles + shared.
//  * support candidates {z - max > -1} pushed to shared (tau >= max-1 always).
//  * tau solved per column by 1 thread: 14 bisections on interval (-1, 0)
//    then Michelot fixed-point (exact at convergence).
//  * output max(z' - tau, 0) streamed back from registers.

#define THREADS 512
#define COLS    8
#define WIDTH   8192
#define ROWS    4096
#define NV4     16        // float4 loads per thread -> 64 floats
#define CAP     256       // candidate buffer per column (expected count ~3-40)

__global__ __launch_bounds__(THREADS, 1)
void sparsemax_cols_kernel(const float* __restrict__ x,
                           const float* __restrict__ a,
                           float* __restrict__ out)
{
    __shared__ float s_wmax[THREADS / 32][COLS];
    __shared__ float s_colmax[COLS];
    __shared__ float s_thr[COLS];
    __shared__ int   s_cnt[COLS];
    __shared__ float s_buf[COLS][CAP];

    const int tid  = threadIdx.x;
    const int lane = tid & 31;
    const int warp = tid >> 5;
    const int q    = tid & 1;           // parity: q=0 -> local cols 0..3, q=1 -> 4..7
    const int c0   = blockIdx.x * COLS; // global column base

    if (tid < COLS) s_cnt[tid] = 0;

    const float scale = -expf(a[0]);

    // ---- load: 16 float4 per thread; z = scale * x ----
    float v[NV4][4];
#pragma unroll
    for (int j = 0; j < NV4; ++j) {
        int f   = tid + j * THREADS;        // flat float4 index in tile
        int row = f >> 1;                   // (f & 1) == q since THREADS is even
        const float4* p = reinterpret_cast<const float4*>(
            x + (size_t)row * WIDTH + c0 + 4 * q);
        float4 t = *p;
        v[j][0] = scale * t.x;
        v[j][1] = scale * t.y;
        v[j][2] = scale * t.z;
        v[j][3] = scale * t.w;
    }

    // ---- per-column max ----
    float m[4] = {-INFINITY, -INFINITY, -INFINITY, -INFINITY};
#pragma unroll
    for (int j = 0; j < NV4; ++j) {
#pragma unroll
        for (int c = 0; c < 4; ++c) m[c] = fmaxf(m[c], v[j][c]);
    }
    // reduce among same-parity lanes (xor by even offsets keeps parity)
#pragma unroll
    for (int off = 2; off <= 16; off <<= 1) {
#pragma unroll
        for (int c = 0; c < 4; ++c)
            m[c] = fmaxf(m[c], __shfl_xor_sync(0xffffffffu, m[c], off));
    }
    if (lane < 2) {
#pragma unroll
        for (int c = 0; c < 4; ++c) s_wmax[warp][lane * 4 + c] = m[c];
    }
    __syncthreads();
    if (tid < COLS) {
        float mm = s_wmax[0][tid];
#pragma unroll
        for (int w = 1; w < THREADS / 32; ++w) mm = fmaxf(mm, s_wmax[w][tid]);
        s_colmax[tid] = mm;
    }
    __syncthreads();

    // ---- shift by column max; collect candidates z' > -1 ----
    float cm[4];
#pragma unroll
    for (int c = 0; c < 4; ++c) cm[c] = s_colmax[4 * q + c];

#pragma unroll
    for (int j = 0; j < NV4; ++j) {
#pragma unroll
        for (int c = 0; c < 4; ++c) {
            float zp = v[j][c] - cm[c];
            v[j][c] = zp;
            if (zp > -1.0f) {
                int col = 4 * q + c;
                int pos = atomicAdd(&s_cnt[col], 1);
                if (pos < CAP) s_buf[col][pos] = zp;
            }
        }
    }
    __syncthreads();

    // ---- solve tau per column (1 thread per column) ----
    if (tid < COLS) {
        int n = s_cnt[tid];
        if (n > CAP) n = CAP;
        const float* b = s_buf[tid];

        // bisection: tau* in (-1, 0); g(tau) = sum max(z'-tau,0) - 1, decreasing
        float lo = -1.0f, hi = 0.0f;
        for (int it = 0; it < 14; ++it) {
            float mid = 0.5f * (lo + hi);
            float g = -1.0f;
            for (int i = 0; i < n; ++i) g += fmaxf(b[i] - mid, 0.0f);
            if (g > 0.0f) lo = mid; else hi = mid;
        }
        // Michelot fixed point from below (lo <= tau*): exact at convergence
        float tau = lo;
        for (int it = 0; it < 16; ++it) {
            float ssum = 0.0f;
            int   k    = 0;
            for (int i = 0; i < n; ++i) {
                float z = b[i];
                if (z > tau) { ssum += z; ++k; }
            }
            float tn = (ssum - 1.0f) / (float)k;   // k >= 1 (z'=0 > tau < 0)
            if (tn == tau) break;
            tau = tn;
        }
        s_thr[tid] = tau;
    }
    __syncthreads();

    // ---- output: max(z' - tau, 0) ----
    float th[4];
#pragma unroll
    for (int c = 0; c < 4; ++c) th[c] = s_thr[4 * q + c];

#pragma unroll
    for (int j = 0; j < NV4; ++j) {
        int f   = tid + j * THREADS;
        int row = f >> 1;
        float4 o;
        o.x = fmaxf(v[j][0] - th[0], 0.0f);
        o.y = fmaxf(v[j][1] - th[1], 0.0f);
        o.z = fmaxf(v[j][2] - th[2], 0.0f);
        o.w = fmaxf(v[j][3] - th[3], 0.0f);
        *reinterpret_cast<float4*>(out + (size_t)row * WIDTH + c0 + 4 * q) = o;
    }
}

extern "C" void kernel_launch(void* const* d_in, const int* in_sizes, int n_in,
                              void* d_out, int out_size)
{
    const float* x = (const float*)d_in[0];
    const float* a = (const float*)d_in[1];
    float* out     = (float*)d_out;

    dim3 grid(WIDTH / COLS);   // 1024 blocks, 8 columns each
    dim3 block(THREADS);
    sparsemax_cols_kernel<<<grid, block>>>(x, a, out);
}